// round 16
// baseline (speedup 1.0000x reference)
#include <cuda_runtime.h>
#include <cuda_fp16.h>
#include <cstdint>
#include <cstddef>

// ---------------- problem constants ----------------
#define B     4
#define Dc    8
#define Hc    32
#define Wc_   32
#define Cin   128
#define Cmid  64
#define Df    16
#define Hf    64
#define Wf    64
#define NPOS  (B*Df*Hf*Wf)
#define BN_EPS 1e-3f
#define NPART 2048

// ---------------- device scratch ----------------
__device__ float g_part[128*NPART];                    // transposed: [ch/sq][cta]
__device__ float g_ss1[128];                           // BN1 scale[64],shift[64]
__device__ float g_ss2[128];

// fp16 operands
__device__ __align__(16) uint16_t g_xa[B*Dc*Hc*Wc_*Cin];
__device__ __align__(16) uint16_t g_ska[(size_t)NPOS*Cmid];
__device__ __align__(16) uint16_t g_y1r[(size_t)NPOS*Cmid];   // raw conv1 out (fp16)
__device__ __align__(16) uint16_t g_y1a[(size_t)NPOS*Cmid];   // BN1+ReLU (fp16)
__device__ __align__(16) uint16_t g_B1[B*8*Cmid*1024];        // [b][par][co][k]
__device__ __align__(16) uint16_t g_B2[B*Cmid*3456];          // [b][co][k]

// ---------------- streams (created at static init) ----------------
struct SideStream {
    cudaStream_t s2, s3; cudaEvent_t e1, e2, e3;
    SideStream() {
        cudaStreamCreateWithFlags(&s2, cudaStreamNonBlocking);
        cudaStreamCreateWithFlags(&s3, cudaStreamNonBlocking);
        cudaEventCreateWithFlags(&e1, cudaEventDisableTiming);
        cudaEventCreateWithFlags(&e2, cudaEventDisableTiming);
        cudaEventCreateWithFlags(&e3, cudaEventDisableTiming);
    }
};
static SideStream g_ss;

// ---------------- PTX helpers (baseline ISA; compiles for plain sm_103) -----
__device__ __forceinline__ uint32_t smem_u32(const void* p) {
    uint32_t a;
    asm("{ .reg .u64 t; cvta.to.shared.u64 t, %1; cvt.u32.u64 %0, t; }" : "=r"(a) : "l"(p));
    return a;
}
__device__ __forceinline__ void ldsm4(uint32_t* r, uint32_t addr) {
    asm volatile("ldmatrix.sync.aligned.m8n8.x4.shared.b16 {%0,%1,%2,%3}, [%4];"
                 : "=r"(r[0]), "=r"(r[1]), "=r"(r[2]), "=r"(r[3]) : "r"(addr));
}
__device__ __forceinline__ void ldsm2(uint32_t* r, uint32_t addr) {
    asm volatile("ldmatrix.sync.aligned.m8n8.x2.shared.b16 {%0,%1}, [%2];"
                 : "=r"(r[0]), "=r"(r[1]) : "r"(addr));
}
__device__ __forceinline__ void mma16816h(float* c, const uint32_t* a, const uint32_t* b) {
    asm volatile("mma.sync.aligned.m16n8k16.row.col.f32.f16.f16.f32 "
                 "{%0,%1,%2,%3}, {%4,%5,%6,%7}, {%8,%9}, {%0,%1,%2,%3};"
                 : "+f"(c[0]), "+f"(c[1]), "+f"(c[2]), "+f"(c[3])
                 : "r"(a[0]), "r"(a[1]), "r"(a[2]), "r"(a[3]), "r"(b[0]), "r"(b[1]));
}
__device__ __forceinline__ void cp16(uint32_t dst, const void* src, uint32_t srcsize) {
    asm volatile("cp.async.cg.shared.global [%0], [%1], 16, %2;"
                 :: "r"(dst), "l"(src), "r"(srcsize) : "memory");
}
#define CP_COMMIT()  asm volatile("cp.async.commit_group;" ::: "memory")
#define CP_WAIT(n)   asm volatile("cp.async.wait_group %0;" :: "n"(n) : "memory")

// ---------------- SMEM layout: XOR-swizzled tiles, 72KB (3-stage ring) -------
#define SA(bf) ((bf)*24576u)
#define SB(bf) ((bf)*24576u + 16384u)
#define SMEM_DYN 73728

// ---------------- fp16 helpers ----------------
__device__ __forceinline__ uint32_t pack2h(float a, float b) {
    return (uint32_t)__half_as_ushort(__float2half_rn(a)) |
           ((uint32_t)__half_as_ushort(__float2half_rn(b)) << 16);
}
__device__ __forceinline__ float2 unpack2h(uint32_t w) {
    return make_float2(__half2float(__ushort_as_half((unsigned short)(w & 0xffffu))),
                       __half2float(__ushort_as_half((unsigned short)(w >> 16))));
}

// ---------------- conv1 weight fold + fp16 pack (fused) ----------------
__device__ __forceinline__ bool tap_in_set(int p, int t, int k) {
    return p ? (t ? (k == 2) : (k <= 1)) : (t ? (k >= 1) : (k == 0));
}
__global__ void pack_b1f(const float* __restrict__ w1) {
    int idx = blockIdx.x * 256 + threadIdx.x;      // 2,097,152 = 4*8*64*1024
    int k   = idx & 1023;
    int co  = (idx >> 10) & 63;
    int par = (idx >> 16) & 7;
    int b   = idx >> 19;
    int tap = k >> 7, ci = k & 127;
    int td = (tap >> 2) & 1, th = (tap >> 1) & 1, tw = tap & 1;
    int pd = (par >> 2) & 1, ph = (par >> 1) & 1, pw = par & 1;
    float s = 0.f;
    #pragma unroll
    for (int kd = 0; kd < 3; ++kd) { if (!tap_in_set(pd, td, kd)) continue;
        #pragma unroll
        for (int kh = 0; kh < 3; ++kh) { if (!tap_in_set(ph, th, kh)) continue;
            #pragma unroll
            for (int kw = 0; kw < 3; ++kw) { if (!tap_in_set(pw, tw, kw)) continue;
                s += w1[((((b*3+kd)*3+kh)*3+kw)*Cin + ci)*Cmid + co]; } } }
    g_B1[(size_t)idx] = __half_as_ushort(__float2half_rn(s));
}

__global__ void pack_b2(const float* __restrict__ w2) {
    int idx = blockIdx.x * 256 + threadIdx.x;      // 884,736
    int k  = idx % 3456;
    int co = (idx / 3456) & 63;
    int b  = idx / (3456*64);
    int tap = k >> 7, ci = k & 127;
    float v = w2[(((size_t)b*27 + tap)*128 + ci)*64 + co];
    g_B2[((size_t)b*64 + co)*3456 + k] = __half_as_ushort(__float2half_rn(v));
}

// fp32 -> fp16 activations, 2 float4s per thread. mode selects dest DEVICE-SIDE.
__global__ void cvt_kernel(const float* __restrict__ src, int n4, int mode) {
    int i0 = blockIdx.x * 512 + threadIdx.x;
    int i1 = i0 + 256;
    uint2* dst = (uint2*)(mode ? g_ska : g_xa);
    float4 v0, v1;
    bool ok0 = i0 < n4, ok1 = i1 < n4;
    if (ok0) v0 = ((const float4*)src)[i0];
    if (ok1) v1 = ((const float4*)src)[i1];
    if (ok0) dst[i0] = make_uint2(pack2h(v0.x, v0.y), pack2h(v0.z, v0.w));
    if (ok1) dst[i1] = make_uint2(pack2h(v1.x, v1.y), pack2h(v1.z, v1.w));
}

// BN1 + ReLU on raw fp16 y1 -> fp16, 8 halves per thread
__global__ void y1bn_cvt() {
    __shared__ float s[128];
    if (threadIdx.x < 128) s[threadIdx.x] = g_ss1[threadIdx.x];
    __syncthreads();
    int i = blockIdx.x * 256 + threadIdx.x;        // grid 8192
    uint4 v = ((const uint4*)g_y1r)[i];
    int cb = (i & 7) * 8;
    float2 a0 = unpack2h(v.x), a1 = unpack2h(v.y), a2 = unpack2h(v.z), a3 = unpack2h(v.w);
    a0.x = fmaxf(fmaf(a0.x, s[cb+0], s[64+cb+0]), 0.f);
    a0.y = fmaxf(fmaf(a0.y, s[cb+1], s[64+cb+1]), 0.f);
    a1.x = fmaxf(fmaf(a1.x, s[cb+2], s[64+cb+2]), 0.f);
    a1.y = fmaxf(fmaf(a1.y, s[cb+3], s[64+cb+3]), 0.f);
    a2.x = fmaxf(fmaf(a2.x, s[cb+4], s[64+cb+4]), 0.f);
    a2.y = fmaxf(fmaf(a2.y, s[cb+5], s[64+cb+5]), 0.f);
    a3.x = fmaxf(fmaf(a3.x, s[cb+6], s[64+cb+6]), 0.f);
    a3.y = fmaxf(fmaf(a3.y, s[cb+7], s[64+cb+7]), 0.f);
    ((uint4*)g_y1a)[i] = make_uint4(pack2h(a0.x, a0.y), pack2h(a1.x, a1.y),
                                    pack2h(a2.x, a2.y), pack2h(a3.x, a3.y));
}

// ---------------- shared GEMM compute: one 64-wide K chunk (fp32 accum) ------
__device__ __forceinline__ void chunk_compute(uint32_t sb, int buf, int wm, int wn, int lid,
                                              float acc[2][4][4]) {
    const uint32_t aT = sb + SA(buf);
    const uint32_t bT = sb + SB(buf);
    #pragma unroll
    for (int ks = 0; ks < 4; ++ks) {
        uint32_t ah[2][4], bh[4][2];
        #pragma unroll
        for (int mt = 0; mt < 2; ++mt) {
            int row = wm*32 + mt*16 + (lid & 15);
            uint32_t g = (uint32_t)(ks*2 + (lid >> 4));
            uint32_t off = (uint32_t)row*128u + ((g ^ ((uint32_t)row & 7u))*16u);
            ldsm4(ah[mt], aT + off);
        }
        #pragma unroll
        for (int nt = 0; nt < 4; ++nt) {
            int row = wn*32 + nt*8 + (lid & 7);
            uint32_t g = (uint32_t)(ks*2 + ((lid >> 3) & 1));
            uint32_t off = (uint32_t)row*128u + ((g ^ ((uint32_t)row & 7u))*16u);
            ldsm2(bh[nt], bT + off);
        }
        #pragma unroll
        for (int mt = 0; mt < 2; ++mt)
            #pragma unroll
            for (int nt = 0; nt < 4; ++nt)
                mma16816h(acc[mt][nt], ah[mt], bh[nt]);
    }
}

// ---------------- fused per-CTA BN stats (transposed partials) ----------------
__device__ __forceinline__ void epilogue_stats(char* smraw, int cta,
                                               int wid, int lid, int t,
                                               const float acc[2][4][4]) {
    float scol[8], qcol[8];
    #pragma unroll
    for (int i = 0; i < 8; ++i) { scol[i] = 0.f; qcol[i] = 0.f; }
    #pragma unroll
    for (int mt = 0; mt < 2; ++mt)
        #pragma unroll
        for (int nt = 0; nt < 4; ++nt) {
            float v0 = acc[mt][nt][0], v1 = acc[mt][nt][1];
            float v2 = acc[mt][nt][2], v3 = acc[mt][nt][3];
            scol[nt*2+0] += v0 + v2; qcol[nt*2+0] += v0*v0 + v2*v2;
            scol[nt*2+1] += v1 + v3; qcol[nt*2+1] += v1*v1 + v3*v3;
        }
    #pragma unroll
    for (int m = 4; m < 32; m <<= 1)
        #pragma unroll
        for (int i = 0; i < 8; ++i) {
            scol[i] += __shfl_xor_sync(0xffffffffu, scol[i], m);
            qcol[i] += __shfl_xor_sync(0xffffffffu, qcol[i], m);
        }
    float* sts = (float*)smraw;
    __syncthreads();
    if (lid < 4) {
        #pragma unroll
        for (int i = 0; i < 8; ++i) {
            int col32 = (i >> 1)*8 + lid*2 + (i & 1);
            sts[wid*32 + col32]       = scol[i];
            sts[256 + wid*32 + col32] = qcol[i];
        }
    }
    __syncthreads();
    if (t < 128) {
        int c = t & 63, isq = t >> 6;
        int wnn = c >> 5, c32 = c & 31;
        float v = 0.f;
        #pragma unroll
        for (int m = 0; m < 4; ++m)
            v += sts[isq*256 + (wnn*4 + m)*32 + c32];
        g_part[(size_t)(isq*64 + c)*NPART + cta] = v;
    }
}

// ---------------- conv1: warp-MMA GEMM, folded 2x2x2 conv, 3-stage ring ------
__global__ void __launch_bounds__(256) conv1_mma() {
    extern __shared__ char smraw[];
    const uint32_t sb = smem_u32(smraw);
    const int b = blockIdx.z, par = blockIdx.y;
    const int pd = (par>>2)&1, phh = (par>>1)&1, pw = par&1;
    const int t = threadIdx.x, wid = t >> 5, lid = t & 31;
    const int wm = wid & 3, wn = wid >> 2;

    const int arow = t >> 1, aseg = t & 1;
    const int m  = blockIdx.x*128 + arow;
    const int mw = m & 31, mh = (m >> 5) & 31, md = m >> 10;
    const int brow = t >> 2;
    const int md_tile = blockIdx.x >> 3;   // md constant across tile

    float acc[2][4][4];
    #pragma unroll
    for (int i = 0; i < 2; ++i)
        #pragma unroll
        for (int j = 0; j < 4; ++j)
            #pragma unroll
            for (int k = 0; k < 4; ++k) acc[i][j][k] = 0.f;

#define C1_ISSUE(CK, BUF) { \
    int tap = (CK) >> 1, cihalf = (CK) & 1; \
    int td = (tap>>2)&1, th = (tap>>1)&1, tw = tap&1; \
    int z = md + (pd ? td : td-1), y = mh + (phh ? th : th-1), xx = mw + (pw ? tw : tw-1); \
    bool valid = ((unsigned)z < 8u) && ((unsigned)y < 32u) && ((unsigned)xx < 32u); \
    size_t sp = valid ? (((size_t)(((b*8+z)*32+y)*32+xx))*128 + (size_t)cihalf*64) : 0; \
    uint32_t szA = valid ? 16u : 0u; \
    _Pragma("unroll") for (int j = 0; j < 4; ++j) { \
        uint32_t g = (uint32_t)(aseg*4 + j); \
        uint32_t dsto = (uint32_t)arow*128u + ((g ^ ((uint32_t)arow & 7u))*16u); \
        cp16(sb + SA(BUF) + dsto, g_xa + sp + g*8, szA); } \
    size_t wb = ((size_t)(b*8+par)*64 + brow)*1024 + (size_t)(CK)*64; \
    _Pragma("unroll") for (int j = 0; j < 2; ++j) { \
        uint32_t gc = (uint32_t)(((t*2 + j) & 7)); \
        uint32_t dsto = (uint32_t)brow*128u + ((gc ^ ((uint32_t)brow & 7u))*16u); \
        cp16(sb + SB(BUF) + dsto, g_B1 + wb + gc*8, 16u); } \
    CP_COMMIT(); \
}

    const int NC = 16;
    C1_ISSUE(0, 0);
    C1_ISSUE(1, 1);
    for (int ck = 0; ck < NC; ++ck) {
        if (ck < NC-1) { CP_WAIT(1); } else { CP_WAIT(0); }
        __syncthreads();
        if (ck + 2 < NC) { C1_ISSUE(ck + 2, (ck + 2) % 3); }
        // dead-chunk skip: tap's depth offset out of range for the whole tile
        int tap = ck >> 1;
        int td = (tap >> 2) & 1;
        int zt = md_tile + (pd ? td : td - 1);
        if ((unsigned)zt < 8u)
            chunk_compute(sb, ck % 3, wm, wn, lid, acc);
    }
#undef C1_ISSUE

    // epilogue: remap to fine coordinates, write raw fp16
    #pragma unroll
    for (int mt = 0; mt < 2; ++mt) {
        int r0 = wm*32 + mt*16 + (lid >> 2);
        #pragma unroll
        for (int half = 0; half < 2; ++half) {
            int mrow = blockIdx.x*128 + r0 + half*8;
            int ww = mrow & 31, hh = (mrow >> 5) & 31, dd = mrow >> 10;
            int od = 2*dd + pd, oh = 2*hh + phh, ow = 2*ww + pw;
            uint16_t* dst = g_y1r + ((size_t)(((b*16+od)*64+oh)*64+ow))*64 + wn*32 + (lid & 3)*2;
            #pragma unroll
            for (int nt = 0; nt < 4; ++nt)
                *(uint32_t*)(dst + nt*8) = pack2h(acc[mt][nt][half*2+0], acc[mt][nt][half*2+1]);
        }
    }
    int cta = (blockIdx.z*8 + blockIdx.y)*64 + blockIdx.x;
    epilogue_stats(smraw, cta, wid, lid, t, acc);
}

// ---------------- conv2: warp-MMA GEMM, 3x3x3, 3-stage ring ------------------
__global__ void __launch_bounds__(256) conv2_mma(float* __restrict__ out) {
    extern __shared__ char smraw[];
    const uint32_t sb = smem_u32(smraw);
    const int b = blockIdx.y;
    const int t = threadIdx.x, wid = t >> 5, lid = t & 31;
    const int wm = wid & 3, wn = wid >> 2;

    const int arow = t >> 1, aseg = t & 1;
    const int m   = blockIdx.x*128 + arow;
    const int ow_ = m & 63, oh_ = (m >> 6) & 63, od_ = m >> 12;
    const int brow = t >> 2;
    const int od_tile = blockIdx.x >> 5;   // od constant across tile

    float acc[2][4][4];
    #pragma unroll
    for (int i = 0; i < 2; ++i)
        #pragma unroll
        for (int j = 0; j < 4; ++j)
            #pragma unroll
            for (int k = 0; k < 4; ++k) acc[i][j][k] = 0.f;

#define C2_ISSUE(CK, BUF) { \
    int tap = (CK) >> 1, cihalf = (CK) & 1; \
    int td = tap/9, r_ = tap%9, th = r_/3, tw = r_%3; \
    int z = od_ + td - 1, y = oh_ + th - 1, xx = ow_ + tw - 1; \
    bool valid = ((unsigned)z < 16u) && ((unsigned)y < 64u) && ((unsigned)xx < 64u); \
    size_t sp = valid ? (((size_t)(((b*16+z)*64+y)*64+xx))*64) : 0; \
    uint32_t szA = valid ? 16u : 0u; \
    const uint16_t* As_ = cihalf ? g_ska : g_y1a; \
    _Pragma("unroll") for (int j = 0; j < 4; ++j) { \
        uint32_t g = (uint32_t)(aseg*4 + j); \
        uint32_t dsto = (uint32_t)arow*128u + ((g ^ ((uint32_t)arow & 7u))*16u); \
        cp16(sb + SA(BUF) + dsto, As_ + sp + g*8, szA); } \
    size_t wb = ((size_t)b*64 + brow)*3456 + (size_t)(CK)*64; \
    _Pragma("unroll") for (int j = 0; j < 2; ++j) { \
        uint32_t gc = (uint32_t)(((t*2 + j) & 7)); \
        uint32_t dsto = (uint32_t)brow*128u + ((gc ^ ((uint32_t)brow & 7u))*16u); \
        cp16(sb + SB(BUF) + dsto, g_B2 + wb + gc*8, 16u); } \
    CP_COMMIT(); \
}

    const int NC = 54;
    C2_ISSUE(0, 0);
    C2_ISSUE(1, 1);
    for (int ck = 0; ck < NC; ++ck) {
        if (ck < NC-1) { CP_WAIT(1); } else { CP_WAIT(0); }
        __syncthreads();
        if (ck + 2 < NC) { C2_ISSUE(ck + 2, (ck + 2) % 3); }
        // dead-chunk skip: depth tap out of range for the whole tile
        int tap = ck >> 1;
        int zt = od_tile + tap/9 - 1;
        if ((unsigned)zt < 16u)
            chunk_compute(sb, ck % 3, wm, wn, lid, acc);
    }
#undef C2_ISSUE

    #pragma unroll
    for (int mt = 0; mt < 2; ++mt) {
        int r0 = wm*32 + mt*16 + (lid >> 2);
        #pragma unroll
        for (int half = 0; half < 2; ++half) {
            int mrow = blockIdx.x*128 + r0 + half*8;
            float* dst = out + ((size_t)b*65536 + mrow)*64 + wn*32 + (lid & 3)*2;
            #pragma unroll
            for (int nt = 0; nt < 4; ++nt) {
                float2 v = make_float2(acc[mt][nt][half*2+0], acc[mt][nt][half*2+1]);
                *(float2*)(dst + nt*8) = v;
            }
        }
    }
    int cta = blockIdx.y*512 + blockIdx.x;
    epilogue_stats(smraw, cta, wid, lid, t, acc);
}

// ---------------- stats reduction: 64 blocks, one channel each ---------------
__global__ void reduce_stats(const float* __restrict__ gamma,
                             const float* __restrict__ beta, int which) {
    const int c = blockIdx.x;          // 0..63
    const int t = threadIdx.x;         // 256
    float s = 0.f, q = 0.f;
    for (int i = t; i < NPART; i += 256) {
        s += g_part[(size_t)c*NPART + i];
        q += g_part[(size_t)(64 + c)*NPART + i];
    }
    __shared__ float shs[256], shq[256];
    shs[t] = s; shq[t] = q;
    __syncthreads();
    for (int st = 128; st > 0; st >>= 1) {
        if (t < st) { shs[t] += shs[t+st]; shq[t] += shq[t+st]; }
        __syncthreads();
    }
    if (t == 0) {
        float mean = shs[0] * (1.f / (float)NPOS);
        float var  = shq[0] * (1.f / (float)NPOS) - mean*mean;
        float sc   = gamma[c] * rsqrtf(var + BN_EPS);
        float sh   = beta[c] - mean * sc;
        float* ss = which ? g_ss1 : g_ss2;
        ss[c] = sc; ss[64 + c] = sh;
    }
}

// BN2 + ReLU in place, 2 float4 per thread
__global__ void bn_relu_kernel(float* __restrict__ out) {
    __shared__ float s[128];
    if (threadIdx.x < 128) s[threadIdx.x] = g_ss2[threadIdx.x];
    __syncthreads();
    size_t i0 = (size_t)blockIdx.x*512 + threadIdx.x;   // grid 8192
    size_t i1 = i0 + 256;
    float4 v0 = ((float4*)out)[i0];
    float4 v1 = ((float4*)out)[i1];
    int cb = ((int)i0 & 15) * 4;
    v0.x = fmaxf(fmaf(v0.x, s[cb+0], s[64+cb+0]), 0.f);
    v0.y = fmaxf(fmaf(v0.y, s[cb+1], s[64+cb+1]), 0.f);
    v0.z = fmaxf(fmaf(v0.z, s[cb+2], s[64+cb+2]), 0.f);
    v0.w = fmaxf(fmaf(v0.w, s[cb+3], s[64+cb+3]), 0.f);
    v1.x = fmaxf(fmaf(v1.x, s[cb+0], s[64+cb+0]), 0.f);
    v1.y = fmaxf(fmaf(v1.y, s[cb+1], s[64+cb+1]), 0.f);
    v1.z = fmaxf(fmaf(v1.z, s[cb+2], s[64+cb+2]), 0.f);
    v1.w = fmaxf(fmaf(v1.w, s[cb+3], s[64+cb+3]), 0.f);
    ((float4*)out)[i0] = v0;
    ((float4*)out)[i1] = v1;
}

// ---------------- launcher ----------------
extern "C" void kernel_launch(void* const* d_in, const int* in_sizes, int n_in,
                              void* d_out, int out_size) {
    (void)in_sizes; (void)n_in; (void)out_size;
    const float* x      = (const float*)d_in[0];
    const float* w1     = (const float*)d_in[1];
    const float* w2     = (const float*)d_in[2];
    const float* skip   = (const float*)d_in[3];
    const float* gamma1 = (const float*)d_in[4];
    const float* beta1  = (const float*)d_in[5];
    const float* gamma2 = (const float*)d_in[6];
    const float* beta2  = (const float*)d_in[7];
    float* out = (float*)d_out;

    cudaFuncSetAttribute(conv1_mma, cudaFuncAttributeMaxDynamicSharedMemorySize, SMEM_DYN);
    cudaFuncSetAttribute(conv2_mma, cudaFuncAttributeMaxDynamicSharedMemorySize, SMEM_DYN);

    // fork A (s2): conv2-only prep overlaps conv1
    cudaEventRecord(g_ss.e1, 0);
    cudaStreamWaitEvent(g_ss.s2, g_ss.e1, 0);
    pack_b2<<<3456, 256, 0, g_ss.s2>>>(w2);
    cvt_kernel<<<8192, 256, 0, g_ss.s2>>>(skip, 4194304, 1);
    cudaEventRecord(g_ss.e2, g_ss.s2);

    // fork B (s3): conv1 weight fold overlaps cvt(x) on main
    cudaStreamWaitEvent(g_ss.s3, g_ss.e1, 0);
    pack_b1f<<<8192, 256, 0, g_ss.s3>>>(w1);
    cudaEventRecord(g_ss.e3, g_ss.s3);

    // main stream: cvt(x), join fork B, conv1
    cvt_kernel<<<2048, 256>>>(x, 1048576, 0);
    cudaStreamWaitEvent(0, g_ss.e3, 0);
    conv1_mma<<<dim3(64, 8, B), 256, SMEM_DYN>>>();
    reduce_stats<<<64, 256>>>(gamma1, beta1, 1);
    y1bn_cvt<<<8192, 256>>>();

    // join fork A, then conv2
    cudaStreamWaitEvent(0, g_ss.e2, 0);
    conv2_mma<<<dim3(512, B), 256, SMEM_DYN>>>(out);
    reduce_stats<<<64, 256>>>(gamma2, beta2, 0);
    bn_relu_kernel<<<8192, 256>>>(out);
}

// round 17
// speedup vs baseline: 1.0091x; 1.0091x over previous
#include <cuda_runtime.h>
#include <cuda_fp16.h>
#include <cstdint>
#include <cstddef>

// ---------------- problem constants ----------------
#define B     4
#define Dc    8
#define Hc    32
#define Wc_   32
#define Cin   128
#define Cmid  64
#define Df    16
#define Hf    64
#define Wf    64
#define NPOS  (B*Df*Hf*Wf)
#define BN_EPS 1e-3f
#define NPART 2048

// ---------------- device scratch ----------------
__device__ float g_part[128*NPART];                    // transposed: [ch/sq][cta]
__device__ float g_ss1[128];                           // BN1 scale[64],shift[64]
__device__ float g_ss2[128];

// fp16 operands
__device__ __align__(16) uint16_t g_xa[B*Dc*Hc*Wc_*Cin];
__device__ __align__(16) uint16_t g_ska[(size_t)NPOS*Cmid];
__device__ __align__(16) uint16_t g_y1r[(size_t)NPOS*Cmid];   // raw conv1 out (fp16)
__device__ __align__(16) uint16_t g_y1a[(size_t)NPOS*Cmid];   // BN1+ReLU (fp16)
__device__ __align__(16) uint16_t g_B1[B*8*Cmid*1024];        // [b][par][co][k]
__device__ __align__(16) uint16_t g_B2[B*Cmid*3456];          // [b][co][k]

// ---------------- streams (created at static init) ----------------
struct SideStream {
    cudaStream_t s2, s3; cudaEvent_t e1, e2, e3;
    SideStream() {
        cudaStreamCreateWithFlags(&s2, cudaStreamNonBlocking);
        cudaStreamCreateWithFlags(&s3, cudaStreamNonBlocking);
        cudaEventCreateWithFlags(&e1, cudaEventDisableTiming);
        cudaEventCreateWithFlags(&e2, cudaEventDisableTiming);
        cudaEventCreateWithFlags(&e3, cudaEventDisableTiming);
    }
};
static SideStream g_ss;

// ---------------- PTX helpers (baseline ISA; compiles for plain sm_103) -----
__device__ __forceinline__ uint32_t smem_u32(const void* p) {
    uint32_t a;
    asm("{ .reg .u64 t; cvta.to.shared.u64 t, %1; cvt.u32.u64 %0, t; }" : "=r"(a) : "l"(p));
    return a;
}
__device__ __forceinline__ void ldsm4(uint32_t* r, uint32_t addr) {
    asm volatile("ldmatrix.sync.aligned.m8n8.x4.shared.b16 {%0,%1,%2,%3}, [%4];"
                 : "=r"(r[0]), "=r"(r[1]), "=r"(r[2]), "=r"(r[3]) : "r"(addr));
}
__device__ __forceinline__ void ldsm2(uint32_t* r, uint32_t addr) {
    asm volatile("ldmatrix.sync.aligned.m8n8.x2.shared.b16 {%0,%1}, [%2];"
                 : "=r"(r[0]), "=r"(r[1]) : "r"(addr));
}
__device__ __forceinline__ void mma16816h(float* c, const uint32_t* a, const uint32_t* b) {
    asm volatile("mma.sync.aligned.m16n8k16.row.col.f32.f16.f16.f32 "
                 "{%0,%1,%2,%3}, {%4,%5,%6,%7}, {%8,%9}, {%0,%1,%2,%3};"
                 : "+f"(c[0]), "+f"(c[1]), "+f"(c[2]), "+f"(c[3])
                 : "r"(a[0]), "r"(a[1]), "r"(a[2]), "r"(a[3]), "r"(b[0]), "r"(b[1]));
}
__device__ __forceinline__ void cp16(uint32_t dst, const void* src, uint32_t srcsize) {
    asm volatile("cp.async.cg.shared.global [%0], [%1], 16, %2;"
                 :: "r"(dst), "l"(src), "r"(srcsize) : "memory");
}
#define CP_COMMIT()  asm volatile("cp.async.commit_group;" ::: "memory")
#define CP_WAIT(n)   asm volatile("cp.async.wait_group %0;" :: "n"(n) : "memory")

// ---------------- SMEM layout: XOR-swizzled tiles, 48KB (double buffer) ------
#define SA(bf) ((bf)*24576u)
#define SB(bf) ((bf)*24576u + 16384u)
#define SMEM_DYN 49152

// ---------------- fp16 helpers ----------------
__device__ __forceinline__ uint32_t pack2h(float a, float b) {
    return (uint32_t)__half_as_ushort(__float2half_rn(a)) |
           ((uint32_t)__half_as_ushort(__float2half_rn(b)) << 16);
}
__device__ __forceinline__ float2 unpack2h(uint32_t w) {
    return make_float2(__half2float(__ushort_as_half((unsigned short)(w & 0xffffu))),
                       __half2float(__ushort_as_half((unsigned short)(w >> 16))));
}

// ---------------- conv1 weight fold + fp16 pack (fused) ----------------
__device__ __forceinline__ bool tap_in_set(int p, int t, int k) {
    return p ? (t ? (k == 2) : (k <= 1)) : (t ? (k >= 1) : (k == 0));
}
__global__ void pack_b1f(const float* __restrict__ w1) {
    int idx = blockIdx.x * 256 + threadIdx.x;      // 2,097,152 = 4*8*64*1024
    int k   = idx & 1023;
    int co  = (idx >> 10) & 63;
    int par = (idx >> 16) & 7;
    int b   = idx >> 19;
    int tap = k >> 7, ci = k & 127;
    int td = (tap >> 2) & 1, th = (tap >> 1) & 1, tw = tap & 1;
    int pd = (par >> 2) & 1, ph = (par >> 1) & 1, pw = par & 1;
    float s = 0.f;
    #pragma unroll
    for (int kd = 0; kd < 3; ++kd) { if (!tap_in_set(pd, td, kd)) continue;
        #pragma unroll
        for (int kh = 0; kh < 3; ++kh) { if (!tap_in_set(ph, th, kh)) continue;
            #pragma unroll
            for (int kw = 0; kw < 3; ++kw) { if (!tap_in_set(pw, tw, kw)) continue;
                s += w1[((((b*3+kd)*3+kh)*3+kw)*Cin + ci)*Cmid + co]; } } }
    g_B1[(size_t)idx] = __half_as_ushort(__float2half_rn(s));
}

__global__ void pack_b2(const float* __restrict__ w2) {
    int idx = blockIdx.x * 256 + threadIdx.x;      // 884,736
    int k  = idx % 3456;
    int co = (idx / 3456) & 63;
    int b  = idx / (3456*64);
    int tap = k >> 7, ci = k & 127;
    float v = w2[(((size_t)b*27 + tap)*128 + ci)*64 + co];
    g_B2[((size_t)b*64 + co)*3456 + k] = __half_as_ushort(__float2half_rn(v));
}

// fp32 -> fp16 activations, 2 float4s per thread. mode selects dest DEVICE-SIDE.
__global__ void cvt_kernel(const float* __restrict__ src, int n4, int mode) {
    int i0 = blockIdx.x * 512 + threadIdx.x;
    int i1 = i0 + 256;
    uint2* dst = (uint2*)(mode ? g_ska : g_xa);
    float4 v0, v1;
    bool ok0 = i0 < n4, ok1 = i1 < n4;
    if (ok0) v0 = ((const float4*)src)[i0];
    if (ok1) v1 = ((const float4*)src)[i1];
    if (ok0) dst[i0] = make_uint2(pack2h(v0.x, v0.y), pack2h(v0.z, v0.w));
    if (ok1) dst[i1] = make_uint2(pack2h(v1.x, v1.y), pack2h(v1.z, v1.w));
}

// BN1 + ReLU on raw fp16 y1 -> fp16, 2 uint4 (16 halves) per thread
__global__ void y1bn_cvt() {
    __shared__ float s[128];
    if (threadIdx.x < 128) s[threadIdx.x] = g_ss1[threadIdx.x];
    __syncthreads();
    int i0 = blockIdx.x * 512 + threadIdx.x;       // grid 4096: 2,097,152 uint4s
    int i1 = i0 + 256;                             // 256 % 8 == 0 -> same cb
    uint4 v0 = ((const uint4*)g_y1r)[i0];
    uint4 v1 = ((const uint4*)g_y1r)[i1];
    int cb = (i0 & 7) * 8;
    #pragma unroll
    for (int p = 0; p < 2; ++p) {
        uint4 v = p ? v1 : v0;
        float2 a0 = unpack2h(v.x), a1 = unpack2h(v.y), a2 = unpack2h(v.z), a3 = unpack2h(v.w);
        a0.x = fmaxf(fmaf(a0.x, s[cb+0], s[64+cb+0]), 0.f);
        a0.y = fmaxf(fmaf(a0.y, s[cb+1], s[64+cb+1]), 0.f);
        a1.x = fmaxf(fmaf(a1.x, s[cb+2], s[64+cb+2]), 0.f);
        a1.y = fmaxf(fmaf(a1.y, s[cb+3], s[64+cb+3]), 0.f);
        a2.x = fmaxf(fmaf(a2.x, s[cb+4], s[64+cb+4]), 0.f);
        a2.y = fmaxf(fmaf(a2.y, s[cb+5], s[64+cb+5]), 0.f);
        a3.x = fmaxf(fmaf(a3.x, s[cb+6], s[64+cb+6]), 0.f);
        a3.y = fmaxf(fmaf(a3.y, s[cb+7], s[64+cb+7]), 0.f);
        ((uint4*)g_y1a)[p ? i1 : i0] = make_uint4(pack2h(a0.x, a0.y), pack2h(a1.x, a1.y),
                                                  pack2h(a2.x, a2.y), pack2h(a3.x, a3.y));
    }
}

// ---------------- shared GEMM compute: one 64-wide K chunk (fp32 accum) ------
__device__ __forceinline__ void chunk_compute(uint32_t sb, int buf, int wm, int wn, int lid,
                                              float acc[2][4][4]) {
    const uint32_t aT = sb + SA(buf);
    const uint32_t bT = sb + SB(buf);
    #pragma unroll
    for (int ks = 0; ks < 4; ++ks) {
        uint32_t ah[2][4], bh[4][2];
        #pragma unroll
        for (int mt = 0; mt < 2; ++mt) {
            int row = wm*32 + mt*16 + (lid & 15);
            uint32_t g = (uint32_t)(ks*2 + (lid >> 4));
            uint32_t off = (uint32_t)row*128u + ((g ^ ((uint32_t)row & 7u))*16u);
            ldsm4(ah[mt], aT + off);
        }
        #pragma unroll
        for (int nt = 0; nt < 4; ++nt) {
            int row = wn*32 + nt*8 + (lid & 7);
            uint32_t g = (uint32_t)(ks*2 + ((lid >> 3) & 1));
            uint32_t off = (uint32_t)row*128u + ((g ^ ((uint32_t)row & 7u))*16u);
            ldsm2(bh[nt], bT + off);
        }
        #pragma unroll
        for (int mt = 0; mt < 2; ++mt)
            #pragma unroll
            for (int nt = 0; nt < 4; ++nt)
                mma16816h(acc[mt][nt], ah[mt], bh[nt]);
    }
}

// ---------------- fused per-CTA BN stats (transposed partials) ----------------
__device__ __forceinline__ void epilogue_stats(char* smraw, int cta,
                                               int wid, int lid, int t,
                                               const float acc[2][4][4]) {
    float scol[8], qcol[8];
    #pragma unroll
    for (int i = 0; i < 8; ++i) { scol[i] = 0.f; qcol[i] = 0.f; }
    #pragma unroll
    for (int mt = 0; mt < 2; ++mt)
        #pragma unroll
        for (int nt = 0; nt < 4; ++nt) {
            float v0 = acc[mt][nt][0], v1 = acc[mt][nt][1];
            float v2 = acc[mt][nt][2], v3 = acc[mt][nt][3];
            scol[nt*2+0] += v0 + v2; qcol[nt*2+0] += v0*v0 + v2*v2;
            scol[nt*2+1] += v1 + v3; qcol[nt*2+1] += v1*v1 + v3*v3;
        }
    #pragma unroll
    for (int m = 4; m < 32; m <<= 1)
        #pragma unroll
        for (int i = 0; i < 8; ++i) {
            scol[i] += __shfl_xor_sync(0xffffffffu, scol[i], m);
            qcol[i] += __shfl_xor_sync(0xffffffffu, qcol[i], m);
        }
    float* sts = (float*)smraw;
    __syncthreads();
    if (lid < 4) {
        #pragma unroll
        for (int i = 0; i < 8; ++i) {
            int col32 = (i >> 1)*8 + lid*2 + (i & 1);
            sts[wid*32 + col32]       = scol[i];
            sts[256 + wid*32 + col32] = qcol[i];
        }
    }
    __syncthreads();
    if (t < 128) {
        int c = t & 63, isq = t >> 6;
        int wnn = c >> 5, c32 = c & 31;
        float v = 0.f;
        #pragma unroll
        for (int m = 0; m < 4; ++m)
            v += sts[isq*256 + (wnn*4 + m)*32 + c32];
        g_part[(size_t)(isq*64 + c)*NPART + cta] = v;
    }
}

// ---------------- conv1: warp-MMA GEMM, folded 2x2x2 conv ----------------
__global__ void __launch_bounds__(256) conv1_mma() {
    extern __shared__ char smraw[];
    const uint32_t sb = smem_u32(smraw);
    const int b = blockIdx.z, par = blockIdx.y;
    const int pd = (par>>2)&1, phh = (par>>1)&1, pw = par&1;
    const int t = threadIdx.x, wid = t >> 5, lid = t & 31;
    const int wm = wid & 3, wn = wid >> 2;

    const int arow = t >> 1, aseg = t & 1;
    const int m  = blockIdx.x*128 + arow;
    const int mw = m & 31, mh = (m >> 5) & 31, md = m >> 10;
    const int brow = t >> 2;
    const int md_tile = blockIdx.x >> 3;   // md constant across tile

    float acc[2][4][4];
    #pragma unroll
    for (int i = 0; i < 2; ++i)
        #pragma unroll
        for (int j = 0; j < 4; ++j)
            #pragma unroll
            for (int k = 0; k < 4; ++k) acc[i][j][k] = 0.f;

#define C1_ISSUE(CK, BUF) { \
    int tap = (CK) >> 1, cihalf = (CK) & 1; \
    int td = (tap>>2)&1, th = (tap>>1)&1, tw = tap&1; \
    int z = md + (pd ? td : td-1), y = mh + (phh ? th : th-1), xx = mw + (pw ? tw : tw-1); \
    bool valid = ((unsigned)z < 8u) && ((unsigned)y < 32u) && ((unsigned)xx < 32u); \
    size_t sp = valid ? (((size_t)(((b*8+z)*32+y)*32+xx))*128 + (size_t)cihalf*64) : 0; \
    uint32_t szA = valid ? 16u : 0u; \
    _Pragma("unroll") for (int j = 0; j < 4; ++j) { \
        uint32_t g = (uint32_t)(aseg*4 + j); \
        uint32_t dsto = (uint32_t)arow*128u + ((g ^ ((uint32_t)arow & 7u))*16u); \
        cp16(sb + SA(BUF) + dsto, g_xa + sp + g*8, szA); } \
    size_t wb = ((size_t)(b*8+par)*64 + brow)*1024 + (size_t)(CK)*64; \
    _Pragma("unroll") for (int j = 0; j < 2; ++j) { \
        uint32_t gc = (uint32_t)(((t*2 + j) & 7)); \
        uint32_t dsto = (uint32_t)brow*128u + ((gc ^ ((uint32_t)brow & 7u))*16u); \
        cp16(sb + SB(BUF) + dsto, g_B1 + wb + gc*8, 16u); } \
    CP_COMMIT(); \
}

    const int NC = 16;
    C1_ISSUE(0, 0);
    C1_ISSUE(1, 1);
    for (int ck = 0; ck < NC; ++ck) {
        if (ck < NC-1) { CP_WAIT(1); } else { CP_WAIT(0); }
        __syncthreads();
        // dead-chunk skip: tap's depth offset out of range for the whole tile
        int tap = ck >> 1;
        int td = (tap >> 2) & 1;
        int zt = md_tile + (pd ? td : td - 1);
        if ((unsigned)zt < 8u)
            chunk_compute(sb, ck & 1, wm, wn, lid, acc);
        __syncthreads();
        if (ck + 2 < NC) { C1_ISSUE(ck + 2, ck & 1); }
    }
#undef C1_ISSUE

    // epilogue: remap to fine coordinates, write raw fp16
    #pragma unroll
    for (int mt = 0; mt < 2; ++mt) {
        int r0 = wm*32 + mt*16 + (lid >> 2);
        #pragma unroll
        for (int half = 0; half < 2; ++half) {
            int mrow = blockIdx.x*128 + r0 + half*8;
            int ww = mrow & 31, hh = (mrow >> 5) & 31, dd = mrow >> 10;
            int od = 2*dd + pd, oh = 2*hh + phh, ow = 2*ww + pw;
            uint16_t* dst = g_y1r + ((size_t)(((b*16+od)*64+oh)*64+ow))*64 + wn*32 + (lid & 3)*2;
            #pragma unroll
            for (int nt = 0; nt < 4; ++nt)
                *(uint32_t*)(dst + nt*8) = pack2h(acc[mt][nt][half*2+0], acc[mt][nt][half*2+1]);
        }
    }
    int cta = (blockIdx.z*8 + blockIdx.y)*64 + blockIdx.x;
    epilogue_stats(smraw, cta, wid, lid, t, acc);
}

// ---------------- conv2: warp-MMA GEMM, 3x3x3 over concat(y1bn, skip) --------
__global__ void __launch_bounds__(256) conv2_mma(float* __restrict__ out) {
    extern __shared__ char smraw[];
    const uint32_t sb = smem_u32(smraw);
    const int b = blockIdx.y;
    const int t = threadIdx.x, wid = t >> 5, lid = t & 31;
    const int wm = wid & 3, wn = wid >> 2;

    const int arow = t >> 1, aseg = t & 1;
    const int m   = blockIdx.x*128 + arow;
    const int ow_ = m & 63, oh_ = (m >> 6) & 63, od_ = m >> 12;
    const int brow = t >> 2;
    const int od_tile = blockIdx.x >> 5;   // od constant across tile

    float acc[2][4][4];
    #pragma unroll
    for (int i = 0; i < 2; ++i)
        #pragma unroll
        for (int j = 0; j < 4; ++j)
            #pragma unroll
            for (int k = 0; k < 4; ++k) acc[i][j][k] = 0.f;

#define C2_ISSUE(CK, BUF) { \
    int tap = (CK) >> 1, cihalf = (CK) & 1; \
    int td = tap/9, r_ = tap%9, th = r_/3, tw = r_%3; \
    int z = od_ + td - 1, y = oh_ + th - 1, xx = ow_ + tw - 1; \
    bool valid = ((unsigned)z < 16u) && ((unsigned)y < 64u) && ((unsigned)xx < 64u); \
    size_t sp = valid ? (((size_t)(((b*16+z)*64+y)*64+xx))*64) : 0; \
    uint32_t szA = valid ? 16u : 0u; \
    const uint16_t* As_ = cihalf ? g_ska : g_y1a; \
    _Pragma("unroll") for (int j = 0; j < 4; ++j) { \
        uint32_t g = (uint32_t)(aseg*4 + j); \
        uint32_t dsto = (uint32_t)arow*128u + ((g ^ ((uint32_t)arow & 7u))*16u); \
        cp16(sb + SA(BUF) + dsto, As_ + sp + g*8, szA); } \
    size_t wb = ((size_t)b*64 + brow)*3456 + (size_t)(CK)*64; \
    _Pragma("unroll") for (int j = 0; j < 2; ++j) { \
        uint32_t gc = (uint32_t)(((t*2 + j) & 7)); \
        uint32_t dsto = (uint32_t)brow*128u + ((gc ^ ((uint32_t)brow & 7u))*16u); \
        cp16(sb + SB(BUF) + dsto, g_B2 + wb + gc*8, 16u); } \
    CP_COMMIT(); \
}

    const int NC = 54;
    C2_ISSUE(0, 0);
    C2_ISSUE(1, 1);
    for (int ck = 0; ck < NC; ++ck) {
        if (ck < NC-1) { CP_WAIT(1); } else { CP_WAIT(0); }
        __syncthreads();
        // dead-chunk skip: depth tap out of range for the whole tile
        int tap = ck >> 1;
        int zt = od_tile + tap/9 - 1;
        if ((unsigned)zt < 16u)
            chunk_compute(sb, ck & 1, wm, wn, lid, acc);
        __syncthreads();
        if (ck + 2 < NC) { C2_ISSUE(ck + 2, ck & 1); }
    }
#undef C2_ISSUE

    #pragma unroll
    for (int mt = 0; mt < 2; ++mt) {
        int r0 = wm*32 + mt*16 + (lid >> 2);
        #pragma unroll
        for (int half = 0; half < 2; ++half) {
            int mrow = blockIdx.x*128 + r0 + half*8;
            float* dst = out + ((size_t)b*65536 + mrow)*64 + wn*32 + (lid & 3)*2;
            #pragma unroll
            for (int nt = 0; nt < 4; ++nt) {
                float2 v = make_float2(acc[mt][nt][half*2+0], acc[mt][nt][half*2+1]);
                *(float2*)(dst + nt*8) = v;
            }
        }
    }
    int cta = blockIdx.y*512 + blockIdx.x;
    epilogue_stats(smraw, cta, wid, lid, t, acc);
}

// ---------------- stats reduction: 64 blocks, one channel each ---------------
__global__ void reduce_stats(const float* __restrict__ gamma,
                             const float* __restrict__ beta, int which) {
    const int c = blockIdx.x;          // 0..63
    const int t = threadIdx.x;         // 256
    float s = 0.f, q = 0.f;
    for (int i = t; i < NPART; i += 256) {
        s += g_part[(size_t)c*NPART + i];
        q += g_part[(size_t)(64 + c)*NPART + i];
    }
    __shared__ float shs[256], shq[256];
    shs[t] = s; shq[t] = q;
    __syncthreads();
    for (int st = 128; st > 0; st >>= 1) {
        if (t < st) { shs[t] += shs[t+st]; shq[t] += shq[t+st]; }
        __syncthreads();
    }
    if (t == 0) {
        float mean = shs[0] * (1.f / (float)NPOS);
        float var  = shq[0] * (1.f / (float)NPOS) - mean*mean;
        float sc   = gamma[c] * rsqrtf(var + BN_EPS);
        float sh   = beta[c] - mean * sc;
        float* ss = which ? g_ss1 : g_ss2;
        ss[c] = sc; ss[64 + c] = sh;
    }
}

// BN2 + ReLU in place, 4 float4 per thread (MLP=4)
__global__ void bn_relu_kernel(float* __restrict__ out) {
    __shared__ float s[128];
    if (threadIdx.x < 128) s[threadIdx.x] = g_ss2[threadIdx.x];
    __syncthreads();
    size_t base = (size_t)blockIdx.x*1024 + threadIdx.x;   // grid 4096
    float4 v[4];
    #pragma unroll
    for (int p = 0; p < 4; ++p) v[p] = ((float4*)out)[base + p*256];
    int cb = ((int)base & 15) * 4;   // +256 preserves cb (256 % 16 == 0)
    #pragma unroll
    for (int p = 0; p < 4; ++p) {
        v[p].x = fmaxf(fmaf(v[p].x, s[cb+0], s[64+cb+0]), 0.f);
        v[p].y = fmaxf(fmaf(v[p].y, s[cb+1], s[64+cb+1]), 0.f);
        v[p].z = fmaxf(fmaf(v[p].z, s[cb+2], s[64+cb+2]), 0.f);
        v[p].w = fmaxf(fmaf(v[p].w, s[cb+3], s[64+cb+3]), 0.f);
    }
    #pragma unroll
    for (int p = 0; p < 4; ++p) ((float4*)out)[base + p*256] = v[p];
}

// ---------------- launcher ----------------
extern "C" void kernel_launch(void* const* d_in, const int* in_sizes, int n_in,
                              void* d_out, int out_size) {
    (void)in_sizes; (void)n_in; (void)out_size;
    const float* x      = (const float*)d_in[0];
    const float* w1     = (const float*)d_in[1];
    const float* w2     = (const float*)d_in[2];
    const float* skip   = (const float*)d_in[3];
    const float* gamma1 = (const float*)d_in[4];
    const float* beta1  = (const float*)d_in[5];
    const float* gamma2 = (const float*)d_in[6];
    const float* beta2  = (const float*)d_in[7];
    float* out = (float*)d_out;

    cudaFuncSetAttribute(conv1_mma, cudaFuncAttributeMaxDynamicSharedMemorySize, SMEM_DYN);
    cudaFuncSetAttribute(conv2_mma, cudaFuncAttributeMaxDynamicSharedMemorySize, SMEM_DYN);

    // fork A (s2): conv2-only prep overlaps conv1
    cudaEventRecord(g_ss.e1, 0);
    cudaStreamWaitEvent(g_ss.s2, g_ss.e1, 0);
    pack_b2<<<3456, 256, 0, g_ss.s2>>>(w2);
    cvt_kernel<<<8192, 256, 0, g_ss.s2>>>(skip, 4194304, 1);
    cudaEventRecord(g_ss.e2, g_ss.s2);

    // fork B (s3): conv1 weight fold overlaps cvt(x) on main
    cudaStreamWaitEvent(g_ss.s3, g_ss.e1, 0);
    pack_b1f<<<8192, 256, 0, g_ss.s3>>>(w1);
    cudaEventRecord(g_ss.e3, g_ss.s3);

    // main stream: cvt(x), join fork B, conv1
    cvt_kernel<<<2048, 256>>>(x, 1048576, 0);
    cudaStreamWaitEvent(0, g_ss.e3, 0);
    conv1_mma<<<dim3(64, 8, B), 256, SMEM_DYN>>>();
    reduce_stats<<<64, 256>>>(gamma1, beta1, 1);
    y1bn_cvt<<<4096, 256>>>();

    // join fork A, then conv2
    cudaStreamWaitEvent(0, g_ss.e2, 0);
    conv2_mma<<<dim3(512, B), 256, SMEM_DYN>>>(out);
    reduce_stats<<<64, 256>>>(gamma2, beta2, 0);
    bn_relu_kernel<<<4096, 256>>>(out);
}